// round 17
// baseline (speedup 1.0000x reference)
#include <cuda_runtime.h>
#include <cuda_fp16.h>
#include <cuda_pipeline.h>
#include <cstdint>

using half_t = __half;

// ---------------- problem constants ----------------
constexpr int BATCH = 2, NTOK = 4160, CDIM = 512, HIDDIM = 2048;
constexpr int NHEADS = 4, HDIM = 128, HSEQ = 4096, SEMN = 64;
constexpr int TOKS = BATCH * NTOK;                       // 8320

// Q scale: 1/sqrt(128) * log2(e)  (softmax via exp2)
#define QSCALE 0.1275174308f

// ---------------- scratch (static device globals, no allocs) ----------------
__device__ __align__(16) half_t g_ln1 [TOKS * CDIM];
__device__ __align__(16) half_t g_q   [BATCH * NHEADS * NTOK * HDIM];
__device__ __align__(16) half_t g_k   [BATCH * NHEADS * NTOK * HDIM];
__device__ __align__(16) half_t g_vT  [BATCH * NHEADS * HDIM * NTOK];
__device__ __align__(16) half_t g_attn[TOKS * CDIM];
__device__ __align__(16) float  g_out1[TOKS * CDIM];
__device__ __align__(16) half_t g_ln2 [TOKS * CDIM];
__device__ __align__(16) half_t g_h1  [BATCH * HSEQ * HIDDIM];
__device__ __align__(16) half_t g_h2  [BATCH * HSEQ * HIDDIM];
__device__ __align__(16) half_t g_sem [BATCH * SEMN * 2 * CDIM];
__device__ __align__(16) half_t g_wqkv[3 * CDIM * CDIM];
__device__ __align__(16) half_t g_wp [CDIM * CDIM];
__device__ __align__(16) half_t g_wf1[HIDDIM * CDIM];
__device__ __align__(16) half_t g_wf2[CDIM * HIDDIM];
__device__ __align__(16) half_t g_wp1[2 * CDIM * CDIM];
__device__ __align__(16) half_t g_wp2[CDIM * 2 * CDIM];
__device__ __align__(16) float  g_bqkv[3 * CDIM];

__device__ __forceinline__ float gelu_exact(float v) {
    return 0.5f * v * (1.f + erff(v * 0.70710678118654752f));
}
__device__ __forceinline__ uint32_t smem_addr(const void* p) {
    return (uint32_t)__cvta_generic_to_shared(p);
}
__device__ __forceinline__ void mma16816h(uint32_t* c, const uint32_t* a,
                                          uint32_t b0, uint32_t b1) {
    asm volatile("mma.sync.aligned.m16n8k16.row.col.f16.f16.f16.f16 "
        "{%0,%1}, {%2,%3,%4,%5}, {%6,%7}, {%0,%1};"
        : "+r"(c[0]), "+r"(c[1])
        : "r"(a[0]), "r"(a[1]), "r"(a[2]), "r"(a[3]), "r"(b0), "r"(b1));
}
__device__ __forceinline__ void ldm4(uint32_t* a, uint32_t saddr) {
    asm volatile("ldmatrix.sync.aligned.m8n8.x4.shared.b16 {%0,%1,%2,%3}, [%4];"
        : "=r"(a[0]), "=r"(a[1]), "=r"(a[2]), "=r"(a[3]) : "r"(saddr));
}

// ================= flash attention (fp16 accum, Q frags hoisted) =================
constexpr int FA_QS  = 0;                 // [128][136] half = 34816
constexpr int FA_KS  = 34816;             // [2][64][136]    = 34816
constexpr int FA_VS  = 69632;             // [2][128][72]    = 36864
constexpr int FA_SMEM = 106496;

__global__ void __launch_bounds__(256, 2) flash_attn(
    const half_t* __restrict__ Q, const half_t* __restrict__ K,
    const half_t* __restrict__ Vt, half_t* __restrict__ Oout)
{
    extern __shared__ __align__(16) unsigned char sm[];
    half_t* Qs = (half_t*)(sm + FA_QS);
    half_t* Ks = (half_t*)(sm + FA_KS);
    half_t* Vs = (half_t*)(sm + FA_VS);

    const int tid = threadIdx.x, w = tid >> 5, lane = tid & 31;
    const int qd = lane >> 2, qc = lane & 3;
    const int bh = blockIdx.y;
    const int m0 = blockIdx.x * 128;

    const half_t* Qg = Q  + (size_t)bh * NTOK * HDIM;
    const half_t* Kg = K  + (size_t)bh * NTOK * HDIM;
    const half_t* Vg = Vt + (size_t)bh * HDIM * NTOK;

#pragma unroll
    for (int i = 0; i < 8; i++) {
        int idx = tid + i * 256, r = idx >> 4, c = (idx & 15) * 8;
        int gr = m0 + r; if (gr >= NTOK) gr = NTOK - 1;
        __pipeline_memcpy_async(Qs + r * 136 + c, Qg + (size_t)gr * HDIM + c, 16);
    }
    __pipeline_commit();
    auto loadKV = [&](int j, int b) {
        const half_t* kg = Kg + (size_t)j * 64 * HDIM;
#pragma unroll
        for (int i = 0; i < 4; i++) {
            int idx = tid + i * 256, r = idx >> 4, c = (idx & 15) * 8;
            __pipeline_memcpy_async(Ks + (b * 64 + r) * 136 + c, kg + r * HDIM + c, 16);
        }
        const half_t* vg = Vg + j * 64;
#pragma unroll
        for (int i = 0; i < 4; i++) {
            int idx = tid + i * 256, r = idx >> 3, c = (idx & 7) * 8;
            __pipeline_memcpy_async(Vs + (b * 128 + r) * 72 + c, vg + (size_t)r * NTOK + c, 16);
        }
    };
    loadKV(0, 0);
    __pipeline_commit();

    const int arow = w * 16 + (lane & 15);
    const int acol = (lane >> 4) << 3;
    const int brow = ((lane >> 3) & 1) * 8 + (lane & 7);
    const int bcol = (lane >> 4) * 8;
    // hoisted per-thread smem bases (bytes)
    const uint32_t qw_ = smem_addr(Qs) + (arow * 136 + acol) * 2;
    const uint32_t kw_ = smem_addr(Ks) + (brow * 136 + bcol) * 2;
    const uint32_t vw_ = smem_addr(Vs) + (brow * 72 + bcol) * 2;

    __pipeline_wait_prior(1);
    __syncthreads();
    uint32_t qf[8][4];
#pragma unroll
    for (int ks = 0; ks < 8; ks++)
        ldm4(qf[ks], qw_ + ks * 32);

    uint32_t O2[16][2];
#pragma unroll
    for (int f = 0; f < 16; f++) { O2[f][0] = 0u; O2[f][1] = 0u; }
    __half2 ls0 = __float2half2_rn(0.f), ls1 = __float2half2_rn(0.f);

    for (int j = 0; j < 65; ++j) {
        const int buf = j & 1;
        __pipeline_wait_prior(0);
        __syncthreads();
        if (j < 64) { loadKV(j + 1, buf ^ 1); __pipeline_commit(); }
        const uint32_t kb_ = kw_ + buf * 17408;   // 64*136*2
        const uint32_t vb_ = vw_ + buf * 18432;   // 128*72*2

        uint32_t S2[8][2];
#pragma unroll
        for (int t = 0; t < 8; t++) { S2[t][0] = 0u; S2[t][1] = 0u; }
#pragma unroll
        for (int ks = 0; ks < 8; ++ks) {
#pragma unroll
            for (int np = 0; np < 4; np++) {
                uint32_t kb[4];
                ldm4(kb, kb_ + np * 4352 + ks * 32);   // 16*136*2 = 4352
                mma16816h(S2[np * 2],     qf[ks], kb[0], kb[2]);
                mma16816h(S2[np * 2 + 1], qf[ks], kb[1], kb[3]);
            }
        }

#pragma unroll
        for (int t = 0; t < 8; t++) {
            __half2 e0 = h2exp2(*reinterpret_cast<__half2*>(&S2[t][0]));
            __half2 e1 = h2exp2(*reinterpret_cast<__half2*>(&S2[t][1]));
            ls0 = __hadd2(ls0, e0);
            ls1 = __hadd2(ls1, e1);
            S2[t][0] = reinterpret_cast<uint32_t&>(e0);
            S2[t][1] = reinterpret_cast<uint32_t&>(e1);
        }

#pragma unroll
        for (int k2 = 0; k2 < 4; k2++) {
            uint32_t pa[4] = {S2[2 * k2][0], S2[2 * k2][1],
                              S2[2 * k2 + 1][0], S2[2 * k2 + 1][1]};
#pragma unroll
            for (int np = 0; np < 8; np++) {
                uint32_t vb[4];
                ldm4(vb, vb_ + np * 2304 + k2 * 32);   // 16*72*2 = 2304
                mma16816h(O2[np * 2],     pa, vb[0], vb[2]);
                mma16816h(O2[np * 2 + 1], pa, vb[1], vb[3]);
            }
        }
    }

    float l0 = __low2float(ls0) + __high2float(ls0);
    float l1 = __low2float(ls1) + __high2float(ls1);
#pragma unroll
    for (int o = 1; o <= 2; o <<= 1) {
        l0 += __shfl_xor_sync(0xffffffffu, l0, o);
        l1 += __shfl_xor_sync(0xffffffffu, l1, o);
    }
    const float i0 = 1.f / l0, i1 = 1.f / l1;

    const int b = bh >> 2, h = bh & 3;
    const int r1 = m0 + w * 16 + qd;
    half_t* Ob = Oout + (size_t)b * NTOK * CDIM + h * HDIM;
#pragma unroll
    for (int f = 0; f < 16; f++) {
        int d = f * 8 + qc * 2;
        __half2 o0 = *reinterpret_cast<__half2*>(&O2[f][0]);
        __half2 o1 = *reinterpret_cast<__half2*>(&O2[f][1]);
        if (r1 < NTOK)
            *reinterpret_cast<__half2*>(Ob + (size_t)r1 * CDIM + d) =
                __floats2half2_rn(__low2float(o0) * i0, __high2float(o0) * i0);
        if (r1 + 8 < NTOK)
            *reinterpret_cast<__half2*>(Ob + (size_t)(r1 + 8) * CDIM + d) =
                __floats2half2_rn(__low2float(o1) * i1, __high2float(o1) * i1);
    }
}

// ===== 128x256x32 GEMM: 8 warps x (64x64 tile), f16 accum, 3-stage, 2 CTAs/SM =====
// mma:ldsm = 4:1. Epilogue in 2 half-passes through Cs[128][132].
// MODE: 0=PLAIN f16(+bias), 1=RESID fp32, 6=GELU f16(+bias), 7=QKV fused scatter
constexpr int GA_ST = 10240;               // A stage bytes (128*40*2)
constexpr int GB_ST = 20480;               // B stage bytes (256*40*2)
constexpr int GB_OFF = 3 * GA_ST;          // 30720
constexpr int G128_SMEM = GB_OFF + 3 * GB_ST;   // 92160 (Cs 67584 overlays)

template<int MODE>
__global__ void __launch_bounds__(256, 2) gemm128(
    const half_t* __restrict__ A, int lda, long long Az, int Aclamp,
    const half_t* __restrict__ B, int ldb, long long Bz, int Bclamp,
    void* __restrict__ outp, int ldc, long long Cz,
    const float* __restrict__ bias,
    const void* __restrict__ aux, long long Rz,
    const float* __restrict__ gamma,
    int K, int Mvalid)
{
    extern __shared__ __align__(16) unsigned char sm[];
    half_t (*As)[40]  = reinterpret_cast<half_t(*)[40]>(sm);
    half_t (*Bs)[40]  = reinterpret_cast<half_t(*)[40]>(sm + GB_OFF);
    float  (*Cs)[132] = reinterpret_cast<float(*)[132]>(sm);

    const int tid = threadIdx.x, wid = tid >> 5, lane = tid & 31;
    const int z  = blockIdx.z;
    const int m0 = blockIdx.y * 128, n0 = blockIdx.x * 256;
    A += (size_t)z * Az;
    B += (size_t)z * Bz;

    auto load = [&](int kt, int s) {
        const int k0 = kt * 32;
#pragma unroll
        for (int i = 0; i < 2; i++) {
            int ch = tid + i * 256;
            int r = ch >> 2, c8 = (ch & 3) * 8;
            int gr = m0 + r; if (gr >= Aclamp) gr = Aclamp - 1;
            __pipeline_memcpy_async(&As[s * 128 + r][c8], A + (size_t)gr * lda + k0 + c8, 16);
        }
#pragma unroll
        for (int i = 0; i < 4; i++) {
            int ch = tid + i * 256;
            int r = ch >> 2, c8 = (ch & 3) * 8;
            int gr = n0 + r; if (gr >= Bclamp) gr = Bclamp - 1;
            __pipeline_memcpy_async(&Bs[s * 256 + r][c8], B + (size_t)gr * ldb + k0 + c8, 16);
        }
    };

    const int wm = wid & 1, wn = wid >> 1;       // warp tile 64x64 at (wm*64, wn*64)
    const int qd = lane >> 2, qc = lane & 3;
    const int ar = lane & 15, ac = (lane >> 4) << 3;
    const int br = ((lane >> 3) & 1) * 8 + (lane & 7), bc = (lane >> 4) * 8;
    // hoisted per-thread smem bases (bytes); stage offsets added in-loop
    const uint32_t aw_ = smem_addr(sm) + ((wm * 64 + ar) * 40 + ac) * 2;
    const uint32_t bw_ = smem_addr(sm + GB_OFF) + ((wn * 64 + br) * 40 + bc) * 2;

    uint32_t acc[4][8][2];                       // [m16][n8][2] f16 half2 pairs = 64 regs
#pragma unroll
    for (int i = 0; i < 4; i++)
#pragma unroll
        for (int j = 0; j < 8; j++) { acc[i][j][0] = 0u; acc[i][j][1] = 0u; }

    const int KT = K >> 5;
    load(0, 0);
    __pipeline_commit();
    load(1, 1);
    __pipeline_commit();
    int s = 0;
    for (int kt = 0; kt < KT; ++kt) {
        if (kt + 1 < KT) __pipeline_wait_prior(1);
        else             __pipeline_wait_prior(0);
        __syncthreads();
        if (kt + 2 < KT) {
            int s2 = s + 2; if (s2 >= 3) s2 -= 3;
            load(kt + 2, s2);
            __pipeline_commit();
        }
        const uint32_t aS = aw_ + s * GA_ST;
        const uint32_t bS = bw_ + s * GB_ST;
#pragma unroll
        for (int kk = 0; kk < 2; ++kk) {
            uint32_t af[4][4];
#pragma unroll
            for (int i = 0; i < 4; i++)
                ldm4(af[i], aS + i * 1280 + kk * 32);           // 16*40*2=1280
#pragma unroll
            for (int j = 0; j < 4; j++) {
                uint32_t kb[4];
                ldm4(kb, bS + j * 1280 + kk * 32);
#pragma unroll
                for (int i = 0; i < 4; i++) {
                    mma16816h(acc[i][j * 2],     af[i], kb[0], kb[2]);
                    mma16816h(acc[i][j * 2 + 1], af[i], kb[1], kb[3]);
                }
            }
        }
        if (++s == 3) s = 0;
    }
    __syncthreads();

    // epilogue: two half-passes (cols [0,128) then [128,256) of the tile)
#pragma unroll
    for (int jh = 0; jh < 2; ++jh) {
        if ((wn >> 1) == jh) {
            const int cbase = (wn & 1) * 64;
#pragma unroll
            for (int i = 0; i < 4; i++)
#pragma unroll
                for (int j = 0; j < 8; j++) {
                    __half2 lo = *reinterpret_cast<__half2*>(&acc[i][j][0]);
                    __half2 hi = *reinterpret_cast<__half2*>(&acc[i][j][1]);
                    int r0 = wm * 64 + i * 16 + qd, c0 = cbase + j * 8 + qc * 2;
                    Cs[r0][c0]     = __low2float(lo);
                    Cs[r0][c0 + 1] = __high2float(lo);
                    Cs[r0 + 8][c0]     = __low2float(hi);
                    Cs[r0 + 8][c0 + 1] = __high2float(hi);
                }
        }
        __syncthreads();
        const int cb = n0 + jh * 128;

        if (MODE == 0 || MODE == 6) {
            for (int it = tid; it < 8192; it += 256) {
                int r = it >> 6, c2 = (it & 63) * 2;
                int m = m0 + r; if (m >= Mvalid) continue;
                float v0 = Cs[r][c2]     + bias[cb + c2];
                float v1 = Cs[r][c2 + 1] + bias[cb + c2 + 1];
                if (MODE == 6) { v0 = gelu_exact(v0); v1 = gelu_exact(v1); }
                *reinterpret_cast<__half2*>(
                    (half_t*)outp + (size_t)z * Cz + (size_t)m * ldc + cb + c2) =
                    __floats2half2_rn(v0, v1);
            }
        } else if (MODE == 1) {
            for (int it = tid; it < 16384; it += 256) {
                int r = it >> 7, c = it & 127;
                int m = m0 + r; if (m >= Mvalid) continue;
                int gc = cb + c;
                float rr = ((const float*)aux)[(size_t)z * Rz + (size_t)m * ldc + gc];
                ((float*)outp)[(size_t)z * Cz + (size_t)m * ldc + gc] =
                    rr + gamma[gc] * (Cs[r][c] + bias[gc]);
            }
        } else if (MODE == 7) {
            if (cb < 2 * CDIM) {             // Q (cb<512) or K (512<=cb<1024)
                const float scale = (cb < CDIM) ? QSCALE : 1.f;
                half_t* base = (cb < CDIM) ? (half_t*)outp : (half_t*)const_cast<void*>(aux);
                const int h = (cb & 511) >> 7;
                for (int it = tid; it < 8192; it += 256) {
                    int r = it >> 6, c2 = (it & 63) * 2;
                    int m = m0 + r; if (m >= Mvalid) continue;
                    int b = m / NTOK, n = m - b * NTOK;
                    int gc = cb + c2, d = gc & 127;
                    float v0 = (Cs[r][c2]     + bias[gc])     * scale;
                    float v1 = (Cs[r][c2 + 1] + bias[gc + 1]) * scale;
                    *reinterpret_cast<__half2*>(
                        base + (((size_t)(b * NHEADS + h)) * NTOK + n) * HDIM + d) =
                        __floats2half2_rn(v0, v1);
                }
            } else {                         // V: transposed scatter (128-col pass = one head)
                half_t* vb = (half_t*)const_cast<float*>(gamma);
                const int h = (cb - 2 * CDIM) >> 7;
                for (int it = tid; it < 16384; it += 256) {
                    int c = it >> 7, r = it & 127;
                    int m = m0 + r; if (m >= Mvalid) continue;
                    int b = m / NTOK, n = m - b * NTOK;
                    float v = Cs[r][c] + bias[cb + c];
                    vb[(((size_t)(b * NHEADS + h)) * HDIM + c) * NTOK + n] = __float2half(v);
                }
            }
        }
        if (jh == 0) __syncthreads();
    }
}

// ---------------- fused fp32->fp16 weight convert + qkv bias concat ----------------
struct CvtArgs {
    const float* s[6];
    half_t* d[6];
    int off[7];
    const float* qb;
    const float* kvb;
    float* bq;
    int total;
};
__global__ void __launch_bounds__(256) cvt_all_kernel(CvtArgs a) {
    int i = blockIdx.x * 256 + threadIdx.x;
    if (i >= a.total) return;
    if (i >= a.off[6]) {
        int j = i - a.off[6];
        a.bq[j] = (j < CDIM) ? a.qb[j] : a.kvb[j - CDIM];
        return;
    }
    int seg = 0;
#pragma unroll
    for (int k = 1; k < 6; k++) seg += (i >= a.off[k]);
    int j = i - a.off[seg];
    a.d[seg][j] = __float2half(a.s[seg][j]);
}

// ---------------- LayerNorm ----------------
__global__ void __launch_bounds__(128) ln_kernel(
    const float* __restrict__ x, const float* __restrict__ w,
    const float* __restrict__ b, half_t* __restrict__ out)
{
    const size_t row = blockIdx.x;
    const int tid = threadIdx.x;
    const float4 v = reinterpret_cast<const float4*>(x + row * CDIM)[tid];
    float s = v.x + v.y + v.z + v.w;
    float q = v.x * v.x + v.y * v.y + v.z * v.z + v.w * v.w;
#pragma unroll
    for (int o = 16; o; o >>= 1) {
        s += __shfl_xor_sync(0xffffffffu, s, o);
        q += __shfl_xor_sync(0xffffffffu, q, o);
    }
    __shared__ float ss[4], qq[4];
    if ((tid & 31) == 0) { ss[tid >> 5] = s; qq[tid >> 5] = q; }
    __syncthreads();
    s = ss[0] + ss[1] + ss[2] + ss[3];
    q = qq[0] + qq[1] + qq[2] + qq[3];
    const float mu = s * (1.f / CDIM);
    const float var = q * (1.f / CDIM) - mu * mu;
    const float rstd = rsqrtf(var + 1e-5f);
    const float4 wv = reinterpret_cast<const float4*>(w)[tid];
    const float4 bv = reinterpret_cast<const float4*>(b)[tid];
    half_t* o = out + row * CDIM + tid * 4;
    *reinterpret_cast<__half2*>(o) =
        __floats2half2_rn((v.x - mu) * rstd * wv.x + bv.x,
                          (v.y - mu) * rstd * wv.y + bv.y);
    *reinterpret_cast<__half2*>(o + 2) =
        __floats2half2_rn((v.z - mu) * rstd * wv.z + bv.z,
                          (v.w - mu) * rstd * wv.w + bv.w);
}

// ---------------- depthwise conv (k=3, pad 1) + bias + exact gelu ----------------
__global__ void __launch_bounds__(256) dwconv_gelu_kernel(
    const half_t* __restrict__ h1, const float* __restrict__ w,
    const float* __restrict__ b, half_t* __restrict__ h2)
{
    size_t idx = (size_t)blockIdx.x * 256 + threadIdx.x;
    int c = (int)(idx & (HIDDIM - 1));
    int n = (int)((idx >> 11) & (HSEQ - 1));
    float x0 = __half2float(h1[idx]);
    float xm = (n > 0)        ? __half2float(h1[idx - HIDDIM]) : 0.f;
    float xp = (n < HSEQ - 1) ? __half2float(h1[idx + HIDDIM]) : 0.f;
    float v = w[c * 3 + 0] * xm + w[c * 3 + 1] * x0 + w[c * 3 + 2] * xp + b[c];
    h2[idx] = __float2half(gelu_exact(v));
}

// ================= host =================
extern "C" void kernel_launch(void* const* d_in, const int* in_sizes, int n_in,
                              void* d_out, int out_size)
{
    (void)in_sizes; (void)n_in; (void)out_size;
    const float* x      = (const float*)d_in[0];
    const float* ln1w   = (const float*)d_in[1];
    const float* ln1b   = (const float*)d_in[2];
    const float* ln2w   = (const float*)d_in[3];
    const float* ln2b   = (const float*)d_in[4];
    const float* qw     = (const float*)d_in[5];
    const float* qb     = (const float*)d_in[6];
    const float* kvw    = (const float*)d_in[7];
    const float* kvb    = (const float*)d_in[8];
    const float* pw     = (const float*)d_in[9];
    const float* pb     = (const float*)d_in[10];
    const float* f1w    = (const float*)d_in[11];
    const float* f1b    = (const float*)d_in[12];
    const float* dww    = (const float*)d_in[13];
    const float* dwb    = (const float*)d_in[14];
    const float* f2w    = (const float*)d_in[15];
    const float* f2b    = (const float*)d_in[16];
    const float* p1w    = (const float*)d_in[17];
    const float* p1b    = (const float*)d_in[18];
    const float* p2w    = (const float*)d_in[19];
    const float* p2b    = (const float*)d_in[20];
    const float* gamma1 = (const float*)d_in[21];
    const float* gamma2 = (const float*)d_in[22];
    float* out = (float*)d_out;

    half_t *ln1, *attn, *ln2, *h1, *h2, *sem, *q, *k, *vT;
    half_t *wqkv, *wp, *wf1, *wf2, *wp1, *wp2;
    float *out1, *bqkv;
    cudaGetSymbolAddress((void**)&ln1,  g_ln1);
    cudaGetSymbolAddress((void**)&q,    g_q);
    cudaGetSymbolAddress((void**)&k,    g_k);
    cudaGetSymbolAddress((void**)&vT,   g_vT);
    cudaGetSymbolAddress((void**)&attn, g_attn);
    cudaGetSymbolAddress((void**)&out1, g_out1);
    cudaGetSymbolAddress((void**)&ln2,  g_ln2);
    cudaGetSymbolAddress((void**)&h1,   g_h1);
    cudaGetSymbolAddress((void**)&h2,   g_h2);
    cudaGetSymbolAddress((void**)&sem,  g_sem);
    cudaGetSymbolAddress((void**)&wqkv, g_wqkv);
    cudaGetSymbolAddress((void**)&wp,   g_wp);
    cudaGetSymbolAddress((void**)&wf1,  g_wf1);
    cudaGetSymbolAddress((void**)&wf2,  g_wf2);
    cudaGetSymbolAddress((void**)&wp1,  g_wp1);
    cudaGetSymbolAddress((void**)&wp2,  g_wp2);
    cudaGetSymbolAddress((void**)&bqkv, g_bqkv);

    cudaFuncSetAttribute(gemm128<0>, cudaFuncAttributeMaxDynamicSharedMemorySize, G128_SMEM);
    cudaFuncSetAttribute(gemm128<1>, cudaFuncAttributeMaxDynamicSharedMemorySize, G128_SMEM);
    cudaFuncSetAttribute(gemm128<6>, cudaFuncAttributeMaxDynamicSharedMemorySize, G128_SMEM);
    cudaFuncSetAttribute(gemm128<7>, cudaFuncAttributeMaxDynamicSharedMemorySize, G128_SMEM);
    cudaFuncSetAttribute(flash_attn, cudaFuncAttributeMaxDynamicSharedMemorySize, FA_SMEM);

    // fused weight conversion + qkv bias concat
    {
        CvtArgs a;
        const float* srcs[6] = {qw, kvw, pw, f1w, f2w, p1w};
        half_t* dsts[6] = {wqkv, wqkv + CDIM * CDIM, wp, wf1, wf2, wp1};
        int ns[6] = {CDIM * CDIM, 2 * CDIM * CDIM, CDIM * CDIM, HIDDIM * CDIM,
                     CDIM * HIDDIM, 2 * CDIM * CDIM};
        int acc = 0;
        for (int i = 0; i < 6; i++) { a.s[i] = srcs[i]; a.d[i] = dsts[i]; a.off[i] = acc; acc += ns[i]; }
        a.off[6] = acc;
        a.qb = qb; a.kvb = kvb; a.bq = bqkv;
        a.total = acc + 3 * CDIM;
        cvt_all_kernel<<<(a.total + 255) / 256, 256>>>(a);
        CvtArgs a2;
        a2.s[0] = p2w; a2.d[0] = wp2; a2.off[0] = 0;
        for (int i = 1; i < 6; i++) { a2.s[i] = p2w; a2.d[i] = wp2; a2.off[i] = CDIM * 2 * CDIM; }
        a2.off[6] = CDIM * 2 * CDIM;
        a2.qb = qb; a2.kvb = kvb; a2.bq = bqkv;
        a2.total = CDIM * 2 * CDIM;
        cvt_all_kernel<<<(a2.total + 255) / 256, 256>>>(a2);
    }

    // LN1
    ln_kernel<<<TOKS, 128>>>(x, ln1w, ln1b, ln1);

    // fused QKV: Q (scaled, fp16) -> q, K -> k, V -> vT   (N = 1536)
    gemm128<7><<<dim3(6, 65, 1), 256, G128_SMEM>>>(
        ln1, CDIM, 0, TOKS, wqkv, CDIM, 0, 3 * CDIM,
        q, 0, 0, bqkv, k, 0, (const float*)vT, CDIM, TOKS);

    // fused attention
    flash_attn<<<dim3(33, 8), 256, FA_SMEM>>>(q, k, vT, attn);

    // out1 = x + gamma1 * (attn @ proj_w^T + proj_b)
    gemm128<1><<<dim3(2, 65, 1), 256, G128_SMEM>>>(
        attn, CDIM, 0, TOKS, wp, CDIM, 0, CDIM,
        out1, CDIM, 0, pb, x, 0, gamma1, CDIM, TOKS);

    // LN2
    ln_kernel<<<TOKS, 128>>>(out1, ln2w, ln2b, ln2);

    // fc1
    gemm128<0><<<dim3(8, 32, BATCH), 256, G128_SMEM>>>(
        ln2, CDIM, (long long)NTOK * CDIM, HSEQ, wf1, CDIM, 0, HIDDIM,
        h1, HIDDIM, (long long)HSEQ * HIDDIM, f1b, nullptr, 0, nullptr, CDIM, HSEQ);

    // dwconv + bias + gelu
    dwconv_gelu_kernel<<<(BATCH * HSEQ * HIDDIM) / 256, 256>>>(h1, dww, dwb, h2);

    // fc2 + residual -> out rows [0,4096) per batch
    gemm128<1><<<dim3(2, 32, BATCH), 256, G128_SMEM>>>(
        h2, HIDDIM, (long long)HSEQ * HIDDIM, HSEQ, wf2, HIDDIM, 0, CDIM,
        out, CDIM, (long long)NTOK * CDIM, f2b,
        out1, (long long)NTOK * CDIM, gamma2, HIDDIM, HSEQ);

    // px1 + gelu
    gemm128<6><<<dim3(4, 1, BATCH), 256, G128_SMEM>>>(
        ln2 + (size_t)HSEQ * CDIM, CDIM, (long long)NTOK * CDIM, SEMN,
        wp1, CDIM, 0, 2 * CDIM,
        sem, 2 * CDIM, (long long)SEMN * 2 * CDIM, p1b,
        nullptr, 0, nullptr, CDIM, SEMN);

    // px2 + residual -> out rows [4096,4160)
    gemm128<1><<<dim3(2, 1, BATCH), 256, G128_SMEM>>>(
        sem, 2 * CDIM, (long long)SEMN * 2 * CDIM, SEMN,
        wp2, 2 * CDIM, 0, CDIM,
        out + (size_t)HSEQ * CDIM, CDIM, (long long)NTOK * CDIM, p2b,
        out1 + (size_t)HSEQ * CDIM, (long long)NTOK * CDIM, gamma2,
        2 * CDIM, SEMN);
}